// round 6
// baseline (speedup 1.0000x reference)
#include <cuda_runtime.h>
#include <cuda_bf16.h>
#include <mma.h>
#include <cstdint>

using namespace nvcuda;

#define DN 64       // EMB_DIM / GEMM N
#define AN 32       // N_ANCHORS
#define KP 96       // combined K (32 dists + 64 embeds)
#define LD 104      // padded smem K stride (elems)
#define ROWS_PB 128

// SMEM byte offsets (main kernel)
#define SM_XHI  0
#define SM_XLO  26624
#define SM_WHI  53248
#define SM_WLO  66560
#define SM_BT   79872          // bias tile [16][64] f32
#define SM_TOTAL 83968

__device__ __nv_bfloat16 g_Whi[DN * KP];   // combined weights hi, [d][k]
__device__ __nv_bfloat16 g_Wlo[DN * KP];   // combined weights lo, [d][k]

// ---------------------------------------------------------------------------
// Fused prep. Block 0: P' = (1/A)·set_emb @ W1 -> g_W{hi,lo}[d][0..31].
// Blocks 1..16: convert W2 rows -> g_W{hi,lo}[d][32..95].
// ---------------------------------------------------------------------------
__global__ __launch_bounds__(256) void prep_kernel(
    const float* __restrict__ embeds,
    const float* __restrict__ W,
    const int*   __restrict__ anchors)
{
    int tid = threadIdx.x;
    if (blockIdx.x == 0) {
        __shared__ int   sA[AN];
        __shared__ float sE[AN][DN];
        if (tid < AN) sA[tid] = anchors[tid];
        __syncthreads();
#pragma unroll
        for (int it = 0; it < 2; it++) {
            int i = tid + it * 256;          // 0..511
            int a = i >> 4, c4 = i & 15;
            float4 v = ((const float4*)(embeds + (size_t)sA[a] * DN))[c4];
            *(float4*)&sE[a][c4 * 4] = v;
        }
        __syncthreads();

        int a  = tid >> 3;                   // 0..31
        int d0 = (tid & 7) * 8;              // 0,8,..,56
        float acc[8] = {0, 0, 0, 0, 0, 0, 0, 0};
#pragma unroll 8
        for (int e = 0; e < DN; e++) {
            float x = sE[a][e];
            float4 w0 = *(const float4*)(W + e * DN + d0);
            float4 w1 = *(const float4*)(W + e * DN + d0 + 4);
            acc[0] = fmaf(x, w0.x, acc[0]);
            acc[1] = fmaf(x, w0.y, acc[1]);
            acc[2] = fmaf(x, w0.z, acc[2]);
            acc[3] = fmaf(x, w0.w, acc[3]);
            acc[4] = fmaf(x, w1.x, acc[4]);
            acc[5] = fmaf(x, w1.y, acc[5]);
            acc[6] = fmaf(x, w1.z, acc[6]);
            acc[7] = fmaf(x, w1.w, acc[7]);
        }
#pragma unroll
        for (int j = 0; j < 8; j++) {
            float w = acc[j] * (1.0f / (float)AN);
            __nv_bfloat16 hi = __float2bfloat16_rn(w);
            __nv_bfloat16 lo = __float2bfloat16_rn(w - __bfloat162float(hi));
            g_Whi[(d0 + j) * KP + a] = hi;
            g_Wlo[(d0 + j) * KP + a] = lo;
        }
    } else {
        int idx = tid + (blockIdx.x - 1) * 256;  // 0..4095
        int k = idx >> 6, d = idx & 63;          // k: local 0..63 -> combined 32..95
        float w = W[(DN + k) * DN + d];          // W2 = W rows 64..127
        __nv_bfloat16 hi = __float2bfloat16_rn(w);
        __nv_bfloat16 lo = __float2bfloat16_rn(w - __bfloat162float(hi));
        g_Whi[d * KP + AN + k] = hi;
        g_Wlo[d * KP + AN + k] = lo;
    }
}

// ---------------------------------------------------------------------------
__device__ __forceinline__ void split2(float a, float b, uint32_t& hi, uint32_t& lo) {
    __nv_bfloat162 h = __floats2bfloat162_rn(a, b);
    float ra = a - __bfloat162float(h.x);
    float rb = b - __bfloat162float(h.y);
    __nv_bfloat162 l = __floats2bfloat162_rn(ra, rb);
    hi = *(uint32_t*)&h;
    lo = *(uint32_t*)&l;
}

// ---------------------------------------------------------------------------
// Main: 128 rows/CTA, 8 warps x (16 rows x 64 cols), bf16-split WMMA.
// Bias preloaded into accumulators; direct store_matrix_sync to gmem.
// ---------------------------------------------------------------------------
__global__ __launch_bounds__(256, 2) void pnn_wmma_kernel(
    const float* __restrict__ embeds,   // [N, 64]
    const float* __restrict__ dists,    // [N, 32]
    const float* __restrict__ bias,     // [64]
    float* __restrict__ out,            // [N, 64]
    int N)
{
    extern __shared__ char smem[];
    __nv_bfloat16* sXhi = (__nv_bfloat16*)(smem + SM_XHI);   // [128][LD]
    __nv_bfloat16* sXlo = (__nv_bfloat16*)(smem + SM_XLO);
    __nv_bfloat16* sWhi = (__nv_bfloat16*)(smem + SM_WHI);   // [64][LD] (col-major B)
    __nv_bfloat16* sWlo = (__nv_bfloat16*)(smem + SM_WLO);
    float*         sBT  = (float*)(smem + SM_BT);            // [16][64] bias tile

    int tid = threadIdx.x;
    int rb = blockIdx.x * ROWS_PB;

    // ---- stage x: dists (k 0..31) ----
#pragma unroll
    for (int it = 0; it < 4; it++) {
        int i = tid + it * 256;
        int r = i >> 3, c4 = i & 7;
        int row = rb + r; if (row >= N) row = N - 1;
        float4 v = ((const float4*)(dists + (size_t)row * AN))[c4];
        int k0 = c4 * 4;
        uint32_t h0, l0, h1, l1;
        split2(v.x, v.y, h0, l0);
        split2(v.z, v.w, h1, l1);
        *(uint2*)(sXhi + r * LD + k0) = make_uint2(h0, h1);
        *(uint2*)(sXlo + r * LD + k0) = make_uint2(l0, l1);
    }
    // ---- stage x: embeds (k 32..95) ----
#pragma unroll
    for (int it = 0; it < 8; it++) {
        int i = tid + it * 256;
        int r = i >> 4, c4 = i & 15;
        int row = rb + r; if (row >= N) row = N - 1;
        float4 v = ((const float4*)(embeds + (size_t)row * DN))[c4];
        int k0 = AN + c4 * 4;
        uint32_t h0, l0, h1, l1;
        split2(v.x, v.y, h0, l0);
        split2(v.z, v.w, h1, l1);
        *(uint2*)(sXhi + r * LD + k0) = make_uint2(h0, h1);
        *(uint2*)(sXlo + r * LD + k0) = make_uint2(l0, l1);
    }
    // ---- stage W hi/lo ----
#pragma unroll
    for (int it = 0; it < 3; it++) {
        int i = tid + it * 256;   // 0..767
        int d = i / 12, kc = i % 12;
        *(uint4*)(sWhi + d * LD + kc * 8) = *(const uint4*)(g_Whi + d * KP + kc * 8);
        *(uint4*)(sWlo + d * LD + kc * 8) = *(const uint4*)(g_Wlo + d * KP + kc * 8);
    }
    // ---- bias tile: 16 identical rows of bias ----
#pragma unroll
    for (int it = 0; it < 4; it++) {
        int i = tid + it * 256;   // 0..1023
        sBT[i] = bias[i & 63];
    }
    __syncthreads();

    // ---- accumulators preloaded with bias ----
    int wid = tid >> 5;
    int r0 = wid * 16;

    wmma::fragment<wmma::accumulator, 16, 16, 16, float> acc[4];
#pragma unroll
    for (int t = 0; t < 4; t++)
        wmma::load_matrix_sync(acc[t], sBT + t * 16, DN, wmma::mem_row_major);
    __syncthreads();   // protect sBT before any (rare) partial-tile scratch reuse

    // ---- single fused K loop: hi*hi + lo*hi + hi*lo ----
#pragma unroll
    for (int ks = 0; ks < KP / 16; ks++) {
        int k0 = ks * 16;
        wmma::fragment<wmma::matrix_a, 16, 16, 16, __nv_bfloat16, wmma::row_major> ah, al;
        wmma::load_matrix_sync(ah, sXhi + r0 * LD + k0, LD);
        wmma::load_matrix_sync(al, sXlo + r0 * LD + k0, LD);
#pragma unroll
        for (int t = 0; t < 4; t++) {
            wmma::fragment<wmma::matrix_b, 16, 16, 16, __nv_bfloat16, wmma::col_major> bh, bl;
            wmma::load_matrix_sync(bh, sWhi + (t * 16) * LD + k0, LD);
            wmma::load_matrix_sync(bl, sWlo + (t * 16) * LD + k0, LD);
            wmma::mma_sync(acc[t], ah, bh, acc[t]);
            wmma::mma_sync(acc[t], al, bh, acc[t]);
            wmma::mma_sync(acc[t], ah, bl, acc[t]);
        }
    }

    // ---- store directly to gmem (per-warp 16-row tile) ----
    int rowbase = rb + r0;
    if (rowbase + 16 <= N) {
        float* op = out + (size_t)rowbase * DN;
#pragma unroll
        for (int t = 0; t < 4; t++)
            wmma::store_matrix_sync(op + t * 16, acc[t], DN, wmma::mem_row_major);
    } else if (rowbase < N) {
        // partial tile (not hit for N % 16 == 0): stage via sBT scratch
#pragma unroll
        for (int t = 0; t < 4; t++)
            wmma::store_matrix_sync(sBT + t * 16, acc[t], DN, wmma::mem_row_major);
        __syncwarp();
        int lane = tid & 31;
#pragma unroll
        for (int q = 0; q < 8; q++) {
            int f4 = lane + q * 32;          // 16 rows x 16 float4
            int r = f4 >> 4, c4 = f4 & 15;
            if (rowbase + r < N)
                ((float4*)(out + (size_t)(rowbase + r) * DN))[c4] =
                    ((const float4*)(sBT + r * DN))[c4];
        }
    }
}

// ---------------------------------------------------------------------------
extern "C" void kernel_launch(void* const* d_in, const int* in_sizes, int n_in,
                              void* d_out, int out_size) {
    const float* embeds  = (const float*)d_in[0];
    const float* dists   = (const float*)d_in[1];
    const float* W       = (const float*)d_in[2];
    const float* bias    = (const float*)d_in[3];
    const int*   anchors = (const int*)  d_in[4];

    int N = in_sizes[0] / DN;   // 100000

    prep_kernel<<<17, 256>>>(embeds, W, anchors);

    cudaFuncSetAttribute(pnn_wmma_kernel,
                         cudaFuncAttributeMaxDynamicSharedMemorySize, SM_TOTAL);
    int blocks = (N + ROWS_PB - 1) / ROWS_PB;
    pnn_wmma_kernel<<<blocks, 256, SM_TOTAL>>>(embeds, dists, bias,
                                               (float*)d_out, N);
}

// round 7
// speedup vs baseline: 1.1963x; 1.1963x over previous
#include <cuda_runtime.h>
#include <cuda_bf16.h>
#include <mma.h>
#include <cstdint>

using namespace nvcuda;

#define DN 64       // EMB_DIM / GEMM N
#define AN 32       // N_ANCHORS
#define KP 96       // combined K (32 dists + 64 embeds)
#define LD 104      // padded smem K stride (elems)
#define ROWS_PB 128

// SMEM byte offsets (main kernel)
#define SM_XHI  0
#define SM_XLO  26624
#define SM_WHI  53248
#define SM_WLO  66560
#define SM_BIAS 79872
#define SM_TOTAL 80128

__device__ __nv_bfloat16 g_Whi[DN * KP];   // combined weights hi, [d][k]
__device__ __nv_bfloat16 g_Wlo[DN * KP];   // combined weights lo, [d][k]

// ---------------------------------------------------------------------------
// Prep, one launch. Blocks 0..7: P' = (1/A)·set_emb @ W1 (4 anchors/block,
// one (a,d) dot per thread). Blocks 8..23: convert W2 rows.
// ---------------------------------------------------------------------------
__global__ __launch_bounds__(256) void prep_kernel(
    const float* __restrict__ embeds,
    const float* __restrict__ W,
    const int*   __restrict__ anchors)
{
    int tid = threadIdx.x;
    int b = blockIdx.x;
    if (b < 8) {
        __shared__ float sE[4][DN];
        if (tid < 64) {
            int a = tid >> 4, c4 = tid & 15;
            long row = (long)anchors[b * 4 + a];
            *(float4*)&sE[a][c4 * 4] =
                ((const float4*)(embeds + row * DN))[c4];
        }
        __syncthreads();

        int al = tid >> 6;            // 0..3 local anchor
        int d  = tid & 63;
        float acc = 0.0f;
#pragma unroll 8
        for (int e = 0; e < DN; e++)
            acc = fmaf(sE[al][e], W[e * DN + d], acc);

        float w = acc * (1.0f / (float)AN);
        __nv_bfloat16 hi = __float2bfloat16_rn(w);
        __nv_bfloat16 lo = __float2bfloat16_rn(w - __bfloat162float(hi));
        int a = b * 4 + al;
        g_Whi[d * KP + a] = hi;
        g_Wlo[d * KP + a] = lo;
    } else {
        int idx = tid + (b - 8) * 256;    // 0..4095
        int k = idx >> 6, d = idx & 63;   // k local 0..63 -> combined 32..95
        float w = W[(DN + k) * DN + d];   // W2 = W rows 64..127
        __nv_bfloat16 hi = __float2bfloat16_rn(w);
        __nv_bfloat16 lo = __float2bfloat16_rn(w - __bfloat162float(hi));
        g_Whi[d * KP + AN + k] = hi;
        g_Wlo[d * KP + AN + k] = lo;
    }
}

// ---------------------------------------------------------------------------
__device__ __forceinline__ void split2(float a, float b, uint32_t& hi, uint32_t& lo) {
    __nv_bfloat162 h = __floats2bfloat162_rn(a, b);
    float ra = a - __bfloat162float(h.x);
    float rb = b - __bfloat162float(h.y);
    __nv_bfloat162 l = __floats2bfloat162_rn(ra, rb);
    hi = *(uint32_t*)&h;
    lo = *(uint32_t*)&l;
}

// ---------------------------------------------------------------------------
// Main (R5 structure): 128 rows/CTA, 8 warps x (16 x 64), bf16-split WMMA.
// ---------------------------------------------------------------------------
__global__ __launch_bounds__(256, 2) void pnn_wmma_kernel(
    const float* __restrict__ embeds,   // [N, 64]
    const float* __restrict__ dists,    // [N, 32]
    const float* __restrict__ bias,     // [64]
    float* __restrict__ out,            // [N, 64]
    int N)
{
    extern __shared__ char smem[];
    __nv_bfloat16* sXhi = (__nv_bfloat16*)(smem + SM_XHI);   // [128][LD]
    __nv_bfloat16* sXlo = (__nv_bfloat16*)(smem + SM_XLO);
    __nv_bfloat16* sWhi = (__nv_bfloat16*)(smem + SM_WHI);   // col-major [64][LD]
    __nv_bfloat16* sWlo = (__nv_bfloat16*)(smem + SM_WLO);
    float*         sB   = (float*)(smem + SM_BIAS);

    int tid = threadIdx.x;
    int rb = blockIdx.x * ROWS_PB;

    // ---- stage x: dists (k 0..31) ----
#pragma unroll
    for (int it = 0; it < 4; it++) {
        int i = tid + it * 256;
        int r = i >> 3, c4 = i & 7;
        int row = rb + r; if (row >= N) row = N - 1;
        float4 v = ((const float4*)(dists + (size_t)row * AN))[c4];
        int k0 = c4 * 4;
        uint32_t h0, l0, h1, l1;
        split2(v.x, v.y, h0, l0);
        split2(v.z, v.w, h1, l1);
        *(uint2*)(sXhi + r * LD + k0) = make_uint2(h0, h1);
        *(uint2*)(sXlo + r * LD + k0) = make_uint2(l0, l1);
    }
    // ---- stage x: embeds (k 32..95) ----
#pragma unroll
    for (int it = 0; it < 8; it++) {
        int i = tid + it * 256;
        int r = i >> 4, c4 = i & 15;
        int row = rb + r; if (row >= N) row = N - 1;
        float4 v = ((const float4*)(embeds + (size_t)row * DN))[c4];
        int k0 = AN + c4 * 4;
        uint32_t h0, l0, h1, l1;
        split2(v.x, v.y, h0, l0);
        split2(v.z, v.w, h1, l1);
        *(uint2*)(sXhi + r * LD + k0) = make_uint2(h0, h1);
        *(uint2*)(sXlo + r * LD + k0) = make_uint2(l0, l1);
    }
    // ---- stage W hi/lo ----
#pragma unroll
    for (int it = 0; it < 3; it++) {
        int i = tid + it * 256;   // 0..767
        int d = i / 12, kc = i % 12;
        *(uint4*)(sWhi + d * LD + kc * 8) = *(const uint4*)(g_Whi + d * KP + kc * 8);
        *(uint4*)(sWlo + d * LD + kc * 8) = *(const uint4*)(g_Wlo + d * KP + kc * 8);
    }
    if (tid < DN) sB[tid] = bias[tid];
    __syncthreads();

    // ---- WMMA ----
    int wid = tid >> 5;
    int r0 = wid * 16;

    wmma::fragment<wmma::accumulator, 16, 16, 16, float> acc[4];
#pragma unroll
    for (int t = 0; t < 4; t++) wmma::fill_fragment(acc[t], 0.0f);

    // passes 1+2 fused (share b_hi): acc += a_hi*b_hi + a_lo*b_hi
#pragma unroll
    for (int ks = 0; ks < KP / 16; ks++) {
        int k0 = ks * 16;
        wmma::fragment<wmma::matrix_a, 16, 16, 16, __nv_bfloat16, wmma::row_major> ah, al;
        wmma::load_matrix_sync(ah, sXhi + r0 * LD + k0, LD);
        wmma::load_matrix_sync(al, sXlo + r0 * LD + k0, LD);
#pragma unroll
        for (int t = 0; t < 4; t++) {
            wmma::fragment<wmma::matrix_b, 16, 16, 16, __nv_bfloat16, wmma::col_major> bh;
            wmma::load_matrix_sync(bh, sWhi + (t * 16) * LD + k0, LD);
            wmma::mma_sync(acc[t], ah, bh, acc[t]);
            wmma::mma_sync(acc[t], al, bh, acc[t]);
        }
    }
    // pass 3: acc += a_hi*b_lo
#pragma unroll
    for (int ks = 0; ks < KP / 16; ks++) {
        int k0 = ks * 16;
        wmma::fragment<wmma::matrix_a, 16, 16, 16, __nv_bfloat16, wmma::row_major> ah;
        wmma::load_matrix_sync(ah, sXhi + r0 * LD + k0, LD);
#pragma unroll
        for (int t = 0; t < 4; t++) {
            wmma::fragment<wmma::matrix_b, 16, 16, 16, __nv_bfloat16, wmma::col_major> bl;
            wmma::load_matrix_sync(bl, sWlo + (t * 16) * LD + k0, LD);
            wmma::mma_sync(acc[t], ah, bl, acc[t]);
        }
    }

    // ---- epilogue: dump frags to smem overlay, add bias, coalesced STG ----
    __syncthreads();   // x/W tiles dead; safe to overlay
    float* epi = (float*)smem;               // [128][64] overlay
    float* wepi = epi + r0 * DN;
#pragma unroll
    for (int t = 0; t < 4; t++)
        wmma::store_matrix_sync(wepi + t * 16, acc[t], DN, wmma::mem_row_major);
    __syncwarp();

    int lane = tid & 31;
#pragma unroll
    for (int q = 0; q < 8; q++) {
        int f4 = lane + q * 32;              // 16 rows x 16 float4
        int r = f4 >> 4, c4 = f4 & 15;
        int row = rb + r0 + r;
        if (row < N) {
            float4 v = ((const float4*)(wepi + r * DN))[c4];
            float4 b4 = ((const float4*)sB)[c4];
            v.x += b4.x; v.y += b4.y; v.z += b4.z; v.w += b4.w;
            ((float4*)(out + (size_t)row * DN))[c4] = v;
        }
    }
}

// ---------------------------------------------------------------------------
extern "C" void kernel_launch(void* const* d_in, const int* in_sizes, int n_in,
                              void* d_out, int out_size) {
    const float* embeds  = (const float*)d_in[0];
    const float* dists   = (const float*)d_in[1];
    const float* W       = (const float*)d_in[2];
    const float* bias    = (const float*)d_in[3];
    const int*   anchors = (const int*)  d_in[4];

    int N = in_sizes[0] / DN;   // 100000

    prep_kernel<<<24, 256>>>(embeds, W, anchors);

    cudaFuncSetAttribute(pnn_wmma_kernel,
                         cudaFuncAttributeMaxDynamicSharedMemorySize, SM_TOTAL);
    int blocks = (N + ROWS_PB - 1) / ROWS_PB;
    pnn_wmma_kernel<<<blocks, 256, SM_TOTAL>>>(embeds, dists, bias,
                                               (float*)d_out, N);
}

// round 8
// speedup vs baseline: 1.2886x; 1.0771x over previous
#include <cuda_runtime.h>
#include <cuda_bf16.h>
#include <mma.h>
#include <cstdint>

using namespace nvcuda;

#define DN 64       // EMB_DIM / GEMM N
#define AN 32       // N_ANCHORS
#define KP 96       // combined K (32 dists + 64 embeds)
#define LD 104      // padded smem K stride (elems)
#define ROWS_PB 128
#define NT 128      // threads per CTA (4 warps)

// SMEM byte offsets (main kernel)
#define SM_XHI  0
#define SM_XLO  26624
#define SM_WHI  53248
#define SM_WLO  66560
#define SM_BIAS 79872
#define SM_TOTAL 80128

__device__ __nv_bfloat16 g_Whi[DN * KP];   // combined weights hi, [d][k]
__device__ __nv_bfloat16 g_Wlo[DN * KP];   // combined weights lo, [d][k]

// ---------------------------------------------------------------------------
// Prep (R7, unchanged). Blocks 0..7: P' rows. Blocks 8..23: W2 convert.
// ---------------------------------------------------------------------------
__global__ __launch_bounds__(256) void prep_kernel(
    const float* __restrict__ embeds,
    const float* __restrict__ W,
    const int*   __restrict__ anchors)
{
    int tid = threadIdx.x;
    int b = blockIdx.x;
    if (b < 8) {
        __shared__ float sE[4][DN];
        if (tid < 64) {
            int a = tid >> 4, c4 = tid & 15;
            long row = (long)anchors[b * 4 + a];
            *(float4*)&sE[a][c4 * 4] =
                ((const float4*)(embeds + row * DN))[c4];
        }
        __syncthreads();

        int al = tid >> 6;            // 0..3 local anchor
        int d  = tid & 63;
        float acc = 0.0f;
#pragma unroll 8
        for (int e = 0; e < DN; e++)
            acc = fmaf(sE[al][e], W[e * DN + d], acc);

        float w = acc * (1.0f / (float)AN);
        __nv_bfloat16 hi = __float2bfloat16_rn(w);
        __nv_bfloat16 lo = __float2bfloat16_rn(w - __bfloat162float(hi));
        int a = b * 4 + al;
        g_Whi[d * KP + a] = hi;
        g_Wlo[d * KP + a] = lo;
    } else {
        int idx = tid + (b - 8) * 256;    // 0..4095
        int k = idx >> 6, d = idx & 63;
        float w = W[(DN + k) * DN + d];
        __nv_bfloat16 hi = __float2bfloat16_rn(w);
        __nv_bfloat16 lo = __float2bfloat16_rn(w - __bfloat162float(hi));
        g_Whi[d * KP + AN + k] = hi;
        g_Wlo[d * KP + AN + k] = lo;
    }
}

// ---------------------------------------------------------------------------
__device__ __forceinline__ void split2(float a, float b, uint32_t& hi, uint32_t& lo) {
    __nv_bfloat162 h = __floats2bfloat162_rn(a, b);
    float ra = a - __bfloat162float(h.x);
    float rb = b - __bfloat162float(h.y);
    __nv_bfloat162 l = __floats2bfloat162_rn(ra, rb);
    hi = *(uint32_t*)&h;
    lo = *(uint32_t*)&l;
}

// ---------------------------------------------------------------------------
// Main: 128 rows/CTA, 4 warps x (32 rows x 64 cols), bf16-split WMMA.
// Fused K loop: per ks, 12 LDSM feed 24 MMAs.
// ---------------------------------------------------------------------------
__global__ __launch_bounds__(NT, 2) void pnn_wmma_kernel(
    const float* __restrict__ embeds,   // [N, 64]
    const float* __restrict__ dists,    // [N, 32]
    const float* __restrict__ bias,     // [64]
    float* __restrict__ out,            // [N, 64]
    int N)
{
    extern __shared__ char smem[];
    __nv_bfloat16* sXhi = (__nv_bfloat16*)(smem + SM_XHI);   // [128][LD]
    __nv_bfloat16* sXlo = (__nv_bfloat16*)(smem + SM_XLO);
    __nv_bfloat16* sWhi = (__nv_bfloat16*)(smem + SM_WHI);   // col-major [64][LD]
    __nv_bfloat16* sWlo = (__nv_bfloat16*)(smem + SM_WLO);
    float*         sB   = (float*)(smem + SM_BIAS);

    int tid = threadIdx.x;
    int rb = blockIdx.x * ROWS_PB;

    // ---- stage x: dists (k 0..31): 1024 float4 ----
#pragma unroll
    for (int it = 0; it < 8; it++) {
        int i = tid + it * NT;
        int r = i >> 3, c4 = i & 7;
        int row = rb + r; if (row >= N) row = N - 1;
        float4 v = ((const float4*)(dists + (size_t)row * AN))[c4];
        int k0 = c4 * 4;
        uint32_t h0, l0, h1, l1;
        split2(v.x, v.y, h0, l0);
        split2(v.z, v.w, h1, l1);
        *(uint2*)(sXhi + r * LD + k0) = make_uint2(h0, h1);
        *(uint2*)(sXlo + r * LD + k0) = make_uint2(l0, l1);
    }
    // ---- stage x: embeds (k 32..95): 2048 float4 ----
#pragma unroll
    for (int it = 0; it < 16; it++) {
        int i = tid + it * NT;
        int r = i >> 4, c4 = i & 15;
        int row = rb + r; if (row >= N) row = N - 1;
        float4 v = ((const float4*)(embeds + (size_t)row * DN))[c4];
        int k0 = AN + c4 * 4;
        uint32_t h0, l0, h1, l1;
        split2(v.x, v.y, h0, l0);
        split2(v.z, v.w, h1, l1);
        *(uint2*)(sXhi + r * LD + k0) = make_uint2(h0, h1);
        *(uint2*)(sXlo + r * LD + k0) = make_uint2(l0, l1);
    }
    // ---- stage W hi/lo: 768 16B chunks each ----
#pragma unroll
    for (int it = 0; it < 6; it++) {
        int i = tid + it * NT;    // 0..767
        int d = i / 12, kc = i % 12;
        *(uint4*)(sWhi + d * LD + kc * 8) = *(const uint4*)(g_Whi + d * KP + kc * 8);
        *(uint4*)(sWlo + d * LD + kc * 8) = *(const uint4*)(g_Wlo + d * KP + kc * 8);
    }
    if (tid < DN) sB[tid] = bias[tid];
    __syncthreads();

    // ---- WMMA: warp tile 32 rows x 64 cols ----
    int wid = tid >> 5;
    int r0 = wid * 32;

    wmma::fragment<wmma::accumulator, 16, 16, 16, float> acc[2][4];
#pragma unroll
    for (int rr = 0; rr < 2; rr++)
#pragma unroll
        for (int t = 0; t < 4; t++) wmma::fill_fragment(acc[rr][t], 0.0f);

#pragma unroll
    for (int ks = 0; ks < KP / 16; ks++) {
        int k0 = ks * 16;
        wmma::fragment<wmma::matrix_a, 16, 16, 16, __nv_bfloat16, wmma::row_major> ah0, ah1, al0, al1;
        wmma::load_matrix_sync(ah0, sXhi + (r0 +  0) * LD + k0, LD);
        wmma::load_matrix_sync(ah1, sXhi + (r0 + 16) * LD + k0, LD);
        wmma::load_matrix_sync(al0, sXlo + (r0 +  0) * LD + k0, LD);
        wmma::load_matrix_sync(al1, sXlo + (r0 + 16) * LD + k0, LD);
#pragma unroll
        for (int t = 0; t < 4; t++) {
            wmma::fragment<wmma::matrix_b, 16, 16, 16, __nv_bfloat16, wmma::col_major> bh, bl;
            wmma::load_matrix_sync(bh, sWhi + (t * 16) * LD + k0, LD);
            wmma::load_matrix_sync(bl, sWlo + (t * 16) * LD + k0, LD);
            wmma::mma_sync(acc[0][t], ah0, bh, acc[0][t]);
            wmma::mma_sync(acc[1][t], ah1, bh, acc[1][t]);
            wmma::mma_sync(acc[0][t], al0, bh, acc[0][t]);
            wmma::mma_sync(acc[1][t], al1, bh, acc[1][t]);
            wmma::mma_sync(acc[0][t], ah0, bl, acc[0][t]);
            wmma::mma_sync(acc[1][t], ah1, bl, acc[1][t]);
        }
    }

    // ---- epilogue: frags -> smem overlay, add bias, coalesced STG ----
    __syncthreads();   // x/W tiles dead; overlay safe
    float* epi = (float*)smem;               // [128][64] overlay (32 KB)
    float* wepi = epi + r0 * DN;
#pragma unroll
    for (int rr = 0; rr < 2; rr++)
#pragma unroll
        for (int t = 0; t < 4; t++)
            wmma::store_matrix_sync(wepi + rr * 16 * DN + t * 16,
                                    acc[rr][t], DN, wmma::mem_row_major);
    __syncwarp();

    int lane = tid & 31;
#pragma unroll
    for (int q = 0; q < 16; q++) {
        int f4 = lane + q * 32;              // 32 rows x 16 float4
        int r = f4 >> 4, c4 = f4 & 15;
        int row = rb + r0 + r;
        if (row < N) {
            float4 v = ((const float4*)(wepi + r * DN))[c4];
            float4 b4 = ((const float4*)sB)[c4];
            v.x += b4.x; v.y += b4.y; v.z += b4.z; v.w += b4.w;
            ((float4*)(out + (size_t)row * DN))[c4] = v;
        }
    }
}

// ---------------------------------------------------------------------------
extern "C" void kernel_launch(void* const* d_in, const int* in_sizes, int n_in,
                              void* d_out, int out_size) {
    const float* embeds  = (const float*)d_in[0];
    const float* dists   = (const float*)d_in[1];
    const float* W       = (const float*)d_in[2];
    const float* bias    = (const float*)d_in[3];
    const int*   anchors = (const int*)  d_in[4];

    int N = in_sizes[0] / DN;   // 100000

    prep_kernel<<<24, 256>>>(embeds, W, anchors);

    cudaFuncSetAttribute(pnn_wmma_kernel,
                         cudaFuncAttributeMaxDynamicSharedMemorySize, SM_TOTAL);
    int blocks = (N + ROWS_PB - 1) / ROWS_PB;
    pnn_wmma_kernel<<<blocks, NT, SM_TOTAL>>>(embeds, dists, bias,
                                              (float*)d_out, N);
}

// round 9
// speedup vs baseline: 1.5151x; 1.1758x over previous
#include <cuda_runtime.h>
#include <cuda_bf16.h>
#include <cstdint>

#define DN 64       // EMB_DIM / GEMM N
#define AN 32       // N_ANCHORS
#define KP 96       // combined K
#define LD 104      // W smem K stride (conflict-free for ldmatrix)
#define ROWS_PB 128
#define NT 128      // 4 warps

__device__ __nv_bfloat16 g_Whi[DN * KP];   // combined weights hi, [d][k]
__device__ __nv_bfloat16 g_Wlo[DN * KP];   // combined weights lo, [d][k]

// ---------------------------------------------------------------------------
// Prep (R7, unchanged). Blocks 0..7: P' rows. Blocks 8..23: W2 convert.
// ---------------------------------------------------------------------------
__global__ __launch_bounds__(256) void prep_kernel(
    const float* __restrict__ embeds,
    const float* __restrict__ W,
    const int*   __restrict__ anchors)
{
    int tid = threadIdx.x;
    int b = blockIdx.x;
    if (b < 8) {
        __shared__ float sE[4][DN];
        if (tid < 64) {
            int a = tid >> 4, c4 = tid & 15;
            long row = (long)anchors[b * 4 + a];
            *(float4*)&sE[a][c4 * 4] =
                ((const float4*)(embeds + row * DN))[c4];
        }
        __syncthreads();
        int al = tid >> 6;
        int d  = tid & 63;
        float acc = 0.0f;
#pragma unroll 8
        for (int e = 0; e < DN; e++)
            acc = fmaf(sE[al][e], W[e * DN + d], acc);
        float w = acc * (1.0f / (float)AN);
        __nv_bfloat16 hi = __float2bfloat16_rn(w);
        __nv_bfloat16 lo = __float2bfloat16_rn(w - __bfloat162float(hi));
        int a = b * 4 + al;
        g_Whi[d * KP + a] = hi;
        g_Wlo[d * KP + a] = lo;
    } else {
        int idx = tid + (b - 8) * 256;
        int k = idx >> 6, d = idx & 63;
        float w = W[(DN + k) * DN + d];
        __nv_bfloat16 hi = __float2bfloat16_rn(w);
        __nv_bfloat16 lo = __float2bfloat16_rn(w - __bfloat162float(hi));
        g_Whi[d * KP + AN + k] = hi;
        g_Wlo[d * KP + AN + k] = lo;
    }
}

// ---------------------------------------------------------------------------
__device__ __forceinline__ void split_f2(float2 v, uint32_t& hi, uint32_t& lo) {
    __nv_bfloat162 h = __floats2bfloat162_rn(v.x, v.y);
    float rx = v.x - __bfloat162float(h.x);
    float ry = v.y - __bfloat162float(h.y);
    __nv_bfloat162 l = __floats2bfloat162_rn(rx, ry);
    hi = *(uint32_t*)&h;
    lo = *(uint32_t*)&l;
}

__device__ __forceinline__ void mma16816(float* c,
                                         uint32_t a0, uint32_t a1,
                                         uint32_t a2, uint32_t a3,
                                         uint32_t b0, uint32_t b1) {
    asm volatile(
        "mma.sync.aligned.m16n8k16.row.col.f32.bf16.bf16.f32 "
        "{%0,%1,%2,%3}, {%4,%5,%6,%7}, {%8,%9}, {%0,%1,%2,%3};"
        : "+f"(c[0]), "+f"(c[1]), "+f"(c[2]), "+f"(c[3])
        : "r"(a0), "r"(a1), "r"(a2), "r"(a3), "r"(b0), "r"(b1));
}

__device__ __forceinline__ void ldsm_x4(uint32_t& r0, uint32_t& r1,
                                        uint32_t& r2, uint32_t& r3,
                                        uint32_t addr) {
    asm volatile(
        "ldmatrix.sync.aligned.m8n8.x4.shared.b16 {%0,%1,%2,%3}, [%4];"
        : "=r"(r0), "=r"(r1), "=r"(r2), "=r"(r3) : "r"(addr));
}

__device__ __forceinline__ uint32_t smem_u32(const void* p) {
    uint32_t a;
    asm("{ .reg .u64 t; cvta.to.shared.u64 t, %1; cvt.u32.u64 %0, t; }"
        : "=r"(a) : "l"(p));
    return a;
}

// ---------------------------------------------------------------------------
// Main: 128 rows/CTA, 4 warps x (32 rows x 64 cols), raw mma.sync bf16-split.
// A fragments built directly from gmem LDG.64 + in-register split (no x smem).
// C stored directly to gmem with bias pre-folded (no epilogue smem).
// ---------------------------------------------------------------------------
__global__ __launch_bounds__(NT, 3) void pnn_mma_kernel(
    const float* __restrict__ embeds,   // [N, 64]
    const float* __restrict__ dists,    // [N, 32]
    const float* __restrict__ bias,     // [64]
    float* __restrict__ out,            // [N, 64]
    int N)
{
    __shared__ __nv_bfloat16 sWhi[DN * LD];
    __shared__ __nv_bfloat16 sWlo[DN * LD];

    int tid = threadIdx.x;

    // ---- stage W hi/lo (768 16B chunks each) ----
#pragma unroll
    for (int it = 0; it < 6; it++) {
        int i = tid + it * NT;
        int d = i / 12, kc = i % 12;
        *(uint4*)(sWhi + d * LD + kc * 8) = *(const uint4*)(g_Whi + d * KP + kc * 8);
        *(uint4*)(sWlo + d * LD + kc * 8) = *(const uint4*)(g_Wlo + d * KP + kc * 8);
    }
    __syncthreads();

    int lane = tid & 31;
    int w    = tid >> 5;
    int g    = lane >> 2;       // 0..7
    int t    = lane & 3;        // 0..3
    int rb   = blockIdx.x * ROWS_PB + w * 32;

    // 4 row indices (R in {0,1}, halves +0/+8), clamped for loads
    int rr[4];
#pragma unroll
    for (int q = 0; q < 4; q++) {
        int row = rb + (q >> 1) * 16 + (q & 1) * 8 + g;
        rr[q] = (row < N) ? row : (N - 1);
    }

    // ldmatrix per-lane address components
    int nrow = ((lane >> 4) & 1) * 8 + (lane & 7);   // n within 16-tile
    int koff = ((lane >> 3) & 1) * 8;                // k half
    uint32_t whi_base = smem_u32(sWhi);
    uint32_t wlo_base = smem_u32(sWlo);

    // ---- acc init = bias ----
    float acc[2][8][4];
#pragma unroll
    for (int n8 = 0; n8 < 8; n8++) {
        float2 bp = *(const float2*)(bias + n8 * 8 + 2 * t);
#pragma unroll
        for (int R = 0; R < 2; R++) {
            acc[R][n8][0] = bp.x; acc[R][n8][1] = bp.y;
            acc[R][n8][2] = bp.x; acc[R][n8][3] = bp.y;
        }
    }

    // ---- main K loop ----
#pragma unroll
    for (int ks = 0; ks < 6; ks++) {
        const float* src = (ks < 2) ? dists : embeds;
        int stride = (ks < 2) ? AN : DN;
        int cb = (ks < 2) ? ks * 16 : ks * 16 - AN;
        int c0 = cb + 2 * t;

        uint32_t ah[2][4], al[2][4];
#pragma unroll
        for (int R = 0; R < 2; R++) {
            const float* p0 = src + (size_t)rr[2 * R]     * stride + c0;
            const float* p1 = src + (size_t)rr[2 * R + 1] * stride + c0;
            split_f2(*(const float2*)(p0),     ah[R][0], al[R][0]);
            split_f2(*(const float2*)(p1),     ah[R][1], al[R][1]);
            split_f2(*(const float2*)(p0 + 8), ah[R][2], al[R][2]);
            split_f2(*(const float2*)(p1 + 8), ah[R][3], al[R][3]);
        }

#pragma unroll
        for (int t16 = 0; t16 < 4; t16++) {
            uint32_t off = (uint32_t)(((t16 * 16 + nrow) * LD + ks * 16 + koff) * 2);
            uint32_t bh0, bh1, bh2, bh3, bl0, bl1, bl2, bl3;
            ldsm_x4(bh0, bh1, bh2, bh3, whi_base + off);
            ldsm_x4(bl0, bl1, bl2, bl3, wlo_base + off);
#pragma unroll
            for (int R = 0; R < 2; R++) {
                float* c0p = acc[R][2 * t16];
                float* c1p = acc[R][2 * t16 + 1];
                mma16816(c0p, ah[R][0], ah[R][1], ah[R][2], ah[R][3], bh0, bh1);
                mma16816(c0p, al[R][0], al[R][1], al[R][2], al[R][3], bh0, bh1);
                mma16816(c0p, ah[R][0], ah[R][1], ah[R][2], ah[R][3], bl0, bl1);
                mma16816(c1p, ah[R][0], ah[R][1], ah[R][2], ah[R][3], bh2, bh3);
                mma16816(c1p, al[R][0], al[R][1], al[R][2], al[R][3], bh2, bh3);
                mma16816(c1p, ah[R][0], ah[R][1], ah[R][2], ah[R][3], bl2, bl3);
            }
        }
    }

    // ---- epilogue: direct STG.64, guarded ----
#pragma unroll
    for (int R = 0; R < 2; R++) {
        int row0 = rb + R * 16 + g;
        int row1 = row0 + 8;
#pragma unroll
        for (int n8 = 0; n8 < 8; n8++) {
            if (row0 < N)
                *(float2*)(out + (size_t)row0 * DN + n8 * 8 + 2 * t) =
                    make_float2(acc[R][n8][0], acc[R][n8][1]);
            if (row1 < N)
                *(float2*)(out + (size_t)row1 * DN + n8 * 8 + 2 * t) =
                    make_float2(acc[R][n8][2], acc[R][n8][3]);
        }
    }
}

// ---------------------------------------------------------------------------
extern "C" void kernel_launch(void* const* d_in, const int* in_sizes, int n_in,
                              void* d_out, int out_size) {
    const float* embeds  = (const float*)d_in[0];
    const float* dists   = (const float*)d_in[1];
    const float* W       = (const float*)d_in[2];
    const float* bias    = (const float*)d_in[3];
    const int*   anchors = (const int*)  d_in[4];

    int N = in_sizes[0] / DN;   // 100000

    prep_kernel<<<24, 256>>>(embeds, W, anchors);

    int blocks = (N + ROWS_PB - 1) / ROWS_PB;
    pnn_mma_kernel<<<blocks, NT>>>(embeds, dists, bias, (float*)d_out, N);
}

// round 10
// speedup vs baseline: 1.6840x; 1.1115x over previous
#include <cuda_runtime.h>
#include <cuda_bf16.h>
#include <cstdint>

#define DN 64       // EMB_DIM / GEMM N
#define AN 32       // N_ANCHORS
#define KP 96       // combined K
#define LD 104      // W smem K stride
#define ROWS_PB 128
#define NT 128      // 4 warps

__device__ __nv_bfloat16 g_Whi[DN * KP];   // permuted combined weights hi
__device__ __nv_bfloat16 g_Wlo[DN * KP];   // permuted combined weights lo

// Within-16 permutation (self-inverse-family index map used for both K and N):
// phys( m ) = 2*((m&15)>>2) + (m&1) + 8*((m>>1)&1), group bits preserved.
__device__ __forceinline__ int perm16(int m) {
    return (m & ~15) | ((((m & 15) >> 2) << 1) | (m & 1) | (((m >> 1) & 1) << 3));
}

// ---------------------------------------------------------------------------
// Prep. Blocks 0..7: P' rows. Blocks 8..23: W2 convert.
// Writes g_W at perm16(d), perm16(k) so the main kernel can use LDG.128 for A
// and STG.128 for C with identity fragment code.
// ---------------------------------------------------------------------------
__global__ __launch_bounds__(256) void prep_kernel(
    const float* __restrict__ embeds,
    const float* __restrict__ W,
    const int*   __restrict__ anchors)
{
    int tid = threadIdx.x;
    int b = blockIdx.x;
    if (b < 8) {
        __shared__ float sE[4][DN];
        if (tid < 64) {
            int a = tid >> 4, c4 = tid & 15;
            long row = (long)anchors[b * 4 + a];
            *(float4*)&sE[a][c4 * 4] =
                ((const float4*)(embeds + row * DN))[c4];
        }
        __syncthreads();
        int al = tid >> 6;
        int d  = tid & 63;
        float acc = 0.0f;
#pragma unroll 8
        for (int e = 0; e < DN; e++)
            acc = fmaf(sE[al][e], W[e * DN + d], acc);
        float w = acc * (1.0f / (float)AN);
        __nv_bfloat16 hi = __float2bfloat16_rn(w);
        __nv_bfloat16 lo = __float2bfloat16_rn(w - __bfloat162float(hi));
        int a = b * 4 + al;
        int dp = perm16(d), ap = perm16(a);
        g_Whi[dp * KP + ap] = hi;
        g_Wlo[dp * KP + ap] = lo;
    } else {
        int idx = tid + (b - 8) * 256;
        int k = idx >> 6, d = idx & 63;
        float w = W[(DN + k) * DN + d];
        __nv_bfloat16 hi = __float2bfloat16_rn(w);
        __nv_bfloat16 lo = __float2bfloat16_rn(w - __bfloat162float(hi));
        int dp = perm16(d), kp = perm16(AN + k);   // AN is 16-aligned
        g_Whi[dp * KP + kp] = hi;
        g_Wlo[dp * KP + kp] = lo;
    }
}

// ---------------------------------------------------------------------------
__device__ __forceinline__ void split_f2(float x, float y, uint32_t& hi, uint32_t& lo) {
    __nv_bfloat162 h = __floats2bfloat162_rn(x, y);
    float rx = x - __bfloat162float(h.x);
    float ry = y - __bfloat162float(h.y);
    __nv_bfloat162 l = __floats2bfloat162_rn(rx, ry);
    hi = *(uint32_t*)&h;
    lo = *(uint32_t*)&l;
}

__device__ __forceinline__ void mma16816(float* c,
                                         uint32_t a0, uint32_t a1,
                                         uint32_t a2, uint32_t a3,
                                         uint32_t b0, uint32_t b1) {
    asm volatile(
        "mma.sync.aligned.m16n8k16.row.col.f32.bf16.bf16.f32 "
        "{%0,%1,%2,%3}, {%4,%5,%6,%7}, {%8,%9}, {%0,%1,%2,%3};"
        : "+f"(c[0]), "+f"(c[1]), "+f"(c[2]), "+f"(c[3])
        : "r"(a0), "r"(a1), "r"(a2), "r"(a3), "r"(b0), "r"(b1));
}

__device__ __forceinline__ void ldsm_x4(uint32_t& r0, uint32_t& r1,
                                        uint32_t& r2, uint32_t& r3,
                                        uint32_t addr) {
    asm volatile(
        "ldmatrix.sync.aligned.m8n8.x4.shared.b16 {%0,%1,%2,%3}, [%4];"
        : "=r"(r0), "=r"(r1), "=r"(r2), "=r"(r3) : "r"(addr));
}

__device__ __forceinline__ uint32_t smem_u32(const void* p) {
    uint32_t a;
    asm("{ .reg .u64 t; cvta.to.shared.u64 t, %1; cvt.u32.u64 %0, t; }"
        : "=r"(a) : "l"(p));
    return a;
}

// ---------------------------------------------------------------------------
// Main: 128 rows/CTA, 4 warps x (32 x 64), raw mma.sync, bf16 split.
// A: LDG.128 straight from gmem (K-permuted weights make layout legal).
// C: STG.128 straight to gmem (N-permuted weights), bias pre-folded.
// ---------------------------------------------------------------------------
__global__ __launch_bounds__(NT, 3) void pnn_mma_kernel(
    const float* __restrict__ embeds,   // [N, 64]
    const float* __restrict__ dists,    // [N, 32]
    const float* __restrict__ bias,     // [64]
    float* __restrict__ out,            // [N, 64]
    int N)
{
    __shared__ __nv_bfloat16 sWhi[DN * LD];
    __shared__ __nv_bfloat16 sWlo[DN * LD];

    int tid = threadIdx.x;

    // ---- stage W hi/lo ----
#pragma unroll
    for (int it = 0; it < 6; it++) {
        int i = tid + it * NT;
        int d = i / 12, kc = i % 12;
        *(uint4*)(sWhi + d * LD + kc * 8) = *(const uint4*)(g_Whi + d * KP + kc * 8);
        *(uint4*)(sWlo + d * LD + kc * 8) = *(const uint4*)(g_Wlo + d * KP + kc * 8);
    }
    __syncthreads();

    int lane = tid & 31;
    int w    = tid >> 5;
    int g    = lane >> 2;       // 0..7
    int t    = lane & 3;        // 0..3
    int rb   = blockIdx.x * ROWS_PB + w * 32;

    // row indices (R in {0,1}, halves +0/+8), clamped for loads
    int rr[4];
#pragma unroll
    for (int q = 0; q < 4; q++) {
        int row = rb + (q >> 1) * 16 + (q & 1) * 8 + g;
        rr[q] = (row < N) ? row : (N - 1);
    }

    int nrow = ((lane >> 4) & 1) * 8 + (lane & 7);
    int koff = ((lane >> 3) & 1) * 8;
    uint32_t whi_base = smem_u32(sWhi);
    uint32_t wlo_base = smem_u32(sWlo);

    // ---- acc init = bias (permuted-N mapping) ----
    // acc[R][2G+q][e] holds logical col G*16 + 4t + 2q + e
    float acc[2][8][4];
#pragma unroll
    for (int G = 0; G < 4; G++) {
        float2 b0 = *(const float2*)(bias + G * 16 + 4 * t);
        float2 b1 = *(const float2*)(bias + G * 16 + 4 * t + 2);
#pragma unroll
        for (int R = 0; R < 2; R++) {
            acc[R][2 * G][0] = b0.x; acc[R][2 * G][1] = b0.y;
            acc[R][2 * G][2] = b0.x; acc[R][2 * G][3] = b0.y;
            acc[R][2 * G + 1][0] = b1.x; acc[R][2 * G + 1][1] = b1.y;
            acc[R][2 * G + 1][2] = b1.x; acc[R][2 * G + 1][3] = b1.y;
        }
    }

    // ---- main K loop: 4 LDG.128 + 8 LDSM -> 24 MMA per ks ----
#pragma unroll
    for (int ks = 0; ks < 6; ks++) {
        const float* src = (ks < 2) ? dists : embeds;
        int stride = (ks < 2) ? AN : DN;
        int cb = (ks < 2) ? ks * 16 : ks * 16 - AN;
        int c0 = cb + 4 * t;

        uint32_t ah[2][4], al[2][4];
#pragma unroll
        for (int R = 0; R < 2; R++) {
            float4 p0 = *(const float4*)(src + (size_t)rr[2 * R]     * stride + c0);
            float4 p1 = *(const float4*)(src + (size_t)rr[2 * R + 1] * stride + c0);
            split_f2(p0.x, p0.y, ah[R][0], al[R][0]);
            split_f2(p1.x, p1.y, ah[R][1], al[R][1]);
            split_f2(p0.z, p0.w, ah[R][2], al[R][2]);
            split_f2(p1.z, p1.w, ah[R][3], al[R][3]);
        }

#pragma unroll
        for (int t16 = 0; t16 < 4; t16++) {
            uint32_t off = (uint32_t)(((t16 * 16 + nrow) * LD + ks * 16 + koff) * 2);
            uint32_t bh0, bh1, bh2, bh3, bl0, bl1, bl2, bl3;
            ldsm_x4(bh0, bh1, bh2, bh3, whi_base + off);
            ldsm_x4(bl0, bl1, bl2, bl3, wlo_base + off);
#pragma unroll
            for (int R = 0; R < 2; R++) {
                float* c0p = acc[R][2 * t16];
                float* c1p = acc[R][2 * t16 + 1];
                mma16816(c0p, ah[R][0], ah[R][1], ah[R][2], ah[R][3], bh0, bh1);
                mma16816(c0p, al[R][0], al[R][1], al[R][2], al[R][3], bh0, bh1);
                mma16816(c0p, ah[R][0], ah[R][1], ah[R][2], ah[R][3], bl0, bl1);
                mma16816(c1p, ah[R][0], ah[R][1], ah[R][2], ah[R][3], bh2, bh3);
                mma16816(c1p, al[R][0], al[R][1], al[R][2], al[R][3], bh2, bh3);
                mma16816(c1p, ah[R][0], ah[R][1], ah[R][2], ah[R][3], bl2, bl3);
            }
        }
    }

    // ---- epilogue: STG.128, logical cols G*16 + 4t + {0..3} ----
#pragma unroll
    for (int R = 0; R < 2; R++) {
        int row0 = rb + R * 16 + g;
        int row1 = row0 + 8;
#pragma unroll
        for (int G = 0; G < 4; G++) {
            if (row0 < N)
                *(float4*)(out + (size_t)row0 * DN + G * 16 + 4 * t) =
                    make_float4(acc[R][2 * G][0], acc[R][2 * G][1],
                                acc[R][2 * G + 1][0], acc[R][2 * G + 1][1]);
            if (row1 < N)
                *(float4*)(out + (size_t)row1 * DN + G * 16 + 4 * t) =
                    make_float4(acc[R][2 * G][2], acc[R][2 * G][3],
                                acc[R][2 * G + 1][2], acc[R][2 * G + 1][3]);
        }
    }
}

// ---------------------------------------------------------------------------
extern "C" void kernel_launch(void* const* d_in, const int* in_sizes, int n_in,
                              void* d_out, int out_size) {
    const float* embeds  = (const float*)d_in[0];
    const float* dists   = (const float*)d_in[1];
    const float* W       = (const float*)d_in[2];
    const float* bias    = (const float*)d_in[3];
    const int*   anchors = (const int*)  d_in[4];

    int N = in_sizes[0] / DN;   // 100000

    prep_kernel<<<24, 256>>>(embeds, W, anchors);

    int blocks = (N + ROWS_PB - 1) / ROWS_PB;
    pnn_mma_kernel<<<blocks, NT>>>(embeds, dists, bias, (float*)d_out, N);
}

// round 11
// speedup vs baseline: 1.6943x; 1.0061x over previous
#include <cuda_runtime.h>
#include <cuda_bf16.h>
#include <cstdint>

#define DN 64       // EMB_DIM / GEMM N
#define AN 32       // N_ANCHORS
#define KP 96       // combined K
#define LD 104      // W smem K stride
#define ROWS_PB 128
#define NT 128      // 4 warps

__device__ __nv_bfloat16 g_Whi[DN * KP];   // permuted combined weights hi
__device__ __nv_bfloat16 g_Wlo[DN * KP];   // permuted combined weights lo

// Within-16 index permutation used for both K and N dims of W.
__device__ __forceinline__ int perm16(int m) {
    return (m & ~15) | ((((m & 15) >> 2) << 1) | (m & 1) | (((m >> 1) & 1) << 3));
}

// ---------------------------------------------------------------------------
// Prep. Blocks 0..7: P' rows. Blocks 8..23: W2 convert. (R10, unchanged)
// ---------------------------------------------------------------------------
__global__ __launch_bounds__(256) void prep_kernel(
    const float* __restrict__ embeds,
    const float* __restrict__ W,
    const int*   __restrict__ anchors)
{
    int tid = threadIdx.x;
    int b = blockIdx.x;
    if (b < 8) {
        __shared__ float sE[4][DN];
        if (tid < 64) {
            int a = tid >> 4, c4 = tid & 15;
            long row = (long)anchors[b * 4 + a];
            *(float4*)&sE[a][c4 * 4] =
                ((const float4*)(embeds + row * DN))[c4];
        }
        __syncthreads();
        int al = tid >> 6;
        int d  = tid & 63;
        float acc = 0.0f;
#pragma unroll 8
        for (int e = 0; e < DN; e++)
            acc = fmaf(sE[al][e], W[e * DN + d], acc);
        float w = acc * (1.0f / (float)AN);
        __nv_bfloat16 hi = __float2bfloat16_rn(w);
        __nv_bfloat16 lo = __float2bfloat16_rn(w - __bfloat162float(hi));
        int a = b * 4 + al;
        g_Whi[perm16(d) * KP + perm16(a)] = hi;
        g_Wlo[perm16(d) * KP + perm16(a)] = lo;
    } else {
        int idx = tid + (b - 8) * 256;
        int k = idx >> 6, d = idx & 63;
        float w = W[(DN + k) * DN + d];
        __nv_bfloat16 hi = __float2bfloat16_rn(w);
        __nv_bfloat16 lo = __float2bfloat16_rn(w - __bfloat162float(hi));
        g_Whi[perm16(d) * KP + perm16(AN + k)] = hi;
        g_Wlo[perm16(d) * KP + perm16(AN + k)] = lo;
    }
}

// ---------------------------------------------------------------------------
__device__ __forceinline__ void split_f2(float x, float y, uint32_t& hi, uint32_t& lo) {
    __nv_bfloat162 h = __floats2bfloat162_rn(x, y);
    float rx = x - __bfloat162float(h.x);
    float ry = y - __bfloat162float(h.y);
    __nv_bfloat162 l = __floats2bfloat162_rn(rx, ry);
    hi = *(uint32_t*)&h;
    lo = *(uint32_t*)&l;
}

__device__ __forceinline__ void mma16816(float* c,
                                         uint32_t a0, uint32_t a1,
                                         uint32_t a2, uint32_t a3,
                                         uint32_t b0, uint32_t b1) {
    asm volatile(
        "mma.sync.aligned.m16n8k16.row.col.f32.bf16.bf16.f32 "
        "{%0,%1,%2,%3}, {%4,%5,%6,%7}, {%8,%9}, {%0,%1,%2,%3};"
        : "+f"(c[0]), "+f"(c[1]), "+f"(c[2]), "+f"(c[3])
        : "r"(a0), "r"(a1), "r"(a2), "r"(a3), "r"(b0), "r"(b1));
}

__device__ __forceinline__ void ldsm_x4(uint32_t& r0, uint32_t& r1,
                                        uint32_t& r2, uint32_t& r3,
                                        uint32_t addr) {
    asm volatile(
        "ldmatrix.sync.aligned.m8n8.x4.shared.b16 {%0,%1,%2,%3}, [%4];"
        : "=r"(r0), "=r"(r1), "=r"(r2), "=r"(r3) : "r"(addr));
}

__device__ __forceinline__ uint32_t smem_u32(const void* p) {
    uint32_t a;
    asm("{ .reg .u64 t; cvta.to.shared.u64 t, %1; cvt.u32.u64 %0, t; }"
        : "=r"(a) : "l"(p));
    return a;
}

// ---------------------------------------------------------------------------
// Main: 128 rows/CTA, 4 warps x (32 x 64), raw mma.sync, bf16 split.
// 2-deep software pipeline on A LDG.128 to bound reg pressure -> 4 CTAs/SM.
// ---------------------------------------------------------------------------
__global__ __launch_bounds__(NT, 4) void pnn_mma_kernel(
    const float* __restrict__ embeds,   // [N, 64]
    const float* __restrict__ dists,    // [N, 32]
    const float* __restrict__ bias,     // [64]
    float* __restrict__ out,            // [N, 64]
    int N)
{
    __shared__ __nv_bfloat16 sWhi[DN * LD];
    __shared__ __nv_bfloat16 sWlo[DN * LD];

    int tid = threadIdx.x;

    // ---- stage W hi/lo (issue LDG+STS; completion covered by syncthreads) ----
#pragma unroll
    for (int it = 0; it < 6; it++) {
        int i = tid + it * NT;
        int d = i / 12, kc = i % 12;
        *(uint4*)(sWhi + d * LD + kc * 8) = *(const uint4*)(g_Whi + d * KP + kc * 8);
        *(uint4*)(sWlo + d * LD + kc * 8) = *(const uint4*)(g_Wlo + d * KP + kc * 8);
    }

    int lane = tid & 31;
    int w    = tid >> 5;
    int g    = lane >> 2;       // 0..7
    int t    = lane & 3;        // 0..3
    int rb   = blockIdx.x * ROWS_PB + w * 32;

    // per-q row base pointers (q = R*2 + half), clamped for loads
    const float* pd[4];
    const float* pe[4];
#pragma unroll
    for (int q = 0; q < 4; q++) {
        int row = rb + (q >> 1) * 16 + (q & 1) * 8 + g;
        int rcl = (row < N) ? row : (N - 1);
        pd[q] = dists  + (size_t)rcl * AN + 4 * t;
        pe[q] = embeds + (size_t)rcl * DN + 4 * t;
    }

    // ---- prefetch ks=0 + bias before the barrier (overlaps W staging) ----
    float4 buf[2][4];
#pragma unroll
    for (int q = 0; q < 4; q++) buf[0][q] = __ldcs((const float4*)pd[q]);

    float2 bv[8];
#pragma unroll
    for (int G = 0; G < 4; G++) {
        bv[2 * G]     = *(const float2*)(bias + G * 16 + 4 * t);
        bv[2 * G + 1] = *(const float2*)(bias + G * 16 + 4 * t + 2);
    }

    __syncthreads();

    int nrow = ((lane >> 4) & 1) * 8 + (lane & 7);
    int koff = ((lane >> 3) & 1) * 8;
    uint32_t whi_base = smem_u32(sWhi);
    uint32_t wlo_base = smem_u32(sWlo);

    // ---- acc init = bias (permuted-N mapping) ----
    float acc[2][8][4];
#pragma unroll
    for (int j = 0; j < 8; j++) {
#pragma unroll
        for (int R = 0; R < 2; R++) {
            acc[R][j][0] = bv[j].x; acc[R][j][1] = bv[j].y;
            acc[R][j][2] = bv[j].x; acc[R][j][3] = bv[j].y;
        }
    }

    // ---- main K loop, 2-deep pipelined A loads ----
#pragma unroll
    for (int ks = 0; ks < 6; ks++) {
        int nk = ks + 1;
        if (nk < 6) {
#pragma unroll
            for (int q = 0; q < 4; q++) {
                const float* p = (nk < 2) ? (pd[q] + nk * 16)
                                          : (pe[q] + (nk - 2) * 16);
                buf[nk & 1][q] = __ldcs((const float4*)p);
            }
        }

        uint32_t ah[2][4], al[2][4];
#pragma unroll
        for (int R = 0; R < 2; R++) {
            float4 p0 = buf[ks & 1][2 * R];
            float4 p1 = buf[ks & 1][2 * R + 1];
            split_f2(p0.x, p0.y, ah[R][0], al[R][0]);
            split_f2(p1.x, p1.y, ah[R][1], al[R][1]);
            split_f2(p0.z, p0.w, ah[R][2], al[R][2]);
            split_f2(p1.z, p1.w, ah[R][3], al[R][3]);
        }

#pragma unroll
        for (int t16 = 0; t16 < 4; t16++) {
            uint32_t off = (uint32_t)(((t16 * 16 + nrow) * LD + ks * 16 + koff) * 2);
            uint32_t bh0, bh1, bh2, bh3, bl0, bl1, bl2, bl3;
            ldsm_x4(bh0, bh1, bh2, bh3, whi_base + off);
            ldsm_x4(bl0, bl1, bl2, bl3, wlo_base + off);
#pragma unroll
            for (int R = 0; R < 2; R++) {
                float* c0p = acc[R][2 * t16];
                float* c1p = acc[R][2 * t16 + 1];
                mma16816(c0p, ah[R][0], ah[R][1], ah[R][2], ah[R][3], bh0, bh1);
                mma16816(c0p, al[R][0], al[R][1], al[R][2], al[R][3], bh0, bh1);
                mma16816(c0p, ah[R][0], ah[R][1], ah[R][2], ah[R][3], bl0, bl1);
                mma16816(c1p, ah[R][0], ah[R][1], ah[R][2], ah[R][3], bh2, bh3);
                mma16816(c1p, al[R][0], al[R][1], al[R][2], al[R][3], bh2, bh3);
                mma16816(c1p, ah[R][0], ah[R][1], ah[R][2], ah[R][3], bl2, bl3);
            }
        }
    }

    // ---- epilogue: STG.128, logical cols G*16 + 4t + {0..3} ----
#pragma unroll
    for (int R = 0; R < 2; R++) {
        int row0 = rb + R * 16 + g;
        int row1 = row0 + 8;
#pragma unroll
        for (int G = 0; G < 4; G++) {
            if (row0 < N)
                *(float4*)(out + (size_t)row0 * DN + G * 16 + 4 * t) =
                    make_float4(acc[R][2 * G][0], acc[R][2 * G][1],
                                acc[R][2 * G + 1][0], acc[R][2 * G + 1][1]);
            if (row1 < N)
                *(float4*)(out + (size_t)row1 * DN + G * 16 + 4 * t) =
                    make_float4(acc[R][2 * G][2], acc[R][2 * G][3],
                                acc[R][2 * G + 1][2], acc[R][2 * G + 1][3]);
        }
    }
}

// ---------------------------------------------------------------------------
extern "C" void kernel_launch(void* const* d_in, const int* in_sizes, int n_in,
                              void* d_out, int out_size) {
    const float* embeds  = (const float*)d_in[0];
    const float* dists   = (const float*)d_in[1];
    const float* W       = (const float*)d_in[2];
    const float* bias    = (const float*)d_in[3];
    const int*   anchors = (const int*)  d_in[4];

    int N = in_sizes[0] / DN;   // 100000

    prep_kernel<<<24, 256>>>(embeds, W, anchors);

    int blocks = (N + ROWS_PB - 1) / ROWS_PB;
    pnn_mma_kernel<<<blocks, NT>>>(embeds, dists, bias, (float*)d_out, N);
}